// round 15
// baseline (speedup 1.0000x reference)
#include <cuda_runtime.h>
#include <cuda_fp16.h>
#include <cstdint>
#include <cstdio>

// Problem constants
#define Bv   32
#define Cv   64
#define Tv   12
#define Nv   1024
#define KSv  3
#define OUTv 64

#define Kdim   (KSv*Nv)        // 3072
#define Mrows  (Bv*Cv*Tv)      // 24576
#define BT     (Bv*Tv)         // 384

// ---------------- scratch ----------------
__device__ __half g_LkH[KSv * Nv * Nv];            // fp16(Lk), natural [k][n][m]
__device__ __half g_YH [(size_t)Mrows * Kdim];     // channel-mix output (fp16)
__device__ __half g_X1 [(size_t)Mrows * Nv];
__device__ __half g_X2 [(size_t)Mrows * Nv];
__device__ __half g_Th1[192 * 64];
__device__ __half g_Th2[192 * 64];
__device__ __half g_FcW[OUTv * Cv];                // fp16(fc_w) [j][o]

static __half *pLkH = nullptr, *pYH = nullptr;
static __half *pX1 = nullptr, *pX2 = nullptr, *pTh1 = nullptr, *pTh2 = nullptr;
static __half *pFcW = nullptr;

// ---- helpers ----
__device__ __forceinline__ void mma_f16(float& c0, float& c1, float& c2, float& c3,
                                        uint32_t a0, uint32_t a1, uint32_t a2, uint32_t a3,
                                        uint32_t b0, uint32_t b1) {
    asm volatile(
        "mma.sync.aligned.m16n8k16.row.col.f32.f16.f16.f32 "
        "{%0,%1,%2,%3}, {%4,%5,%6,%7}, {%8,%9}, {%0,%1,%2,%3};"
        : "+f"(c0), "+f"(c1), "+f"(c2), "+f"(c3)
        : "r"(a0), "r"(a1), "r"(a2), "r"(a3), "r"(b0), "r"(b1));
}

__device__ __forceinline__ void ldsm_x4(uint32_t& r0, uint32_t& r1, uint32_t& r2, uint32_t& r3,
                                        uint32_t addr) {
    asm volatile("ldmatrix.sync.aligned.m8n8.x4.shared.b16 {%0,%1,%2,%3}, [%4];"
                 : "=r"(r0), "=r"(r1), "=r"(r2), "=r"(r3) : "r"(addr));
}
__device__ __forceinline__ void ldsm_x4_t(uint32_t& r0, uint32_t& r1, uint32_t& r2, uint32_t& r3,
                                          uint32_t addr) {
    asm volatile("ldmatrix.sync.aligned.m8n8.x4.trans.shared.b16 {%0,%1,%2,%3}, [%4];"
                 : "=r"(r0), "=r"(r1), "=r"(r2), "=r"(r3) : "r"(addr));
}

__device__ __forceinline__ void cp16(uint32_t dst_smem, const void* src) {
    asm volatile("cp.async.cg.shared.global [%0], [%1], 16;" :: "r"(dst_smem), "l"(src));
}
__device__ __forceinline__ void cp_commit() { asm volatile("cp.async.commit_group;"); }

// ---------------- prep: Lk + thetas + fcw, ONE launch ----------------
__global__ __launch_bounds__(256) void prep_all(const float* __restrict__ Lk,
                                                const float* __restrict__ th1,
                                                const float* __restrict__ th2,
                                                const float* __restrict__ fcw,
                                                __half* __restrict__ LkH,
                                                __half* __restrict__ o1,
                                                __half* __restrict__ o2,
                                                __half* __restrict__ fcwH)
{
    int bid = blockIdx.x;
    if (bid < 3072) {
        size_t i = (size_t)bid * 1024 + threadIdx.x * 4;
        float4 v = *reinterpret_cast<const float4*>(Lk + i);
        *reinterpret_cast<__half2*>(LkH + i)     = __floats2half2_rn(v.x, v.y);
        *reinterpret_cast<__half2*>(LkH + i + 2) = __floats2half2_rn(v.z, v.w);
    } else if (bid < 3168) {
        int b2 = bid - 3072;                 // 0..95
        const float* src = (b2 >= 48) ? th2 : th1;
        __half*      dst = (b2 >= 48) ? o2  : o1;
        int idx = (b2 % 48) * 256 + threadIdx.x;
        int i = idx / 192;
        int p = idx - i * 192;
        dst[p * 64 + i] = __float2half_rn(src[idx]);
    } else {
        for (int i = threadIdx.x; i < OUTv * Cv; i += 256)
            fcwH[i] = __float2half_rn(fcw[i]);
    }
}

// ---------------- kernel B: channel mix, split-p (96 rows/CTA) --------------
// Y[p=(o,k)][m] = sum_i thT[p][i] * X[i][m];  CTA: 96 p-rows x 128 m.
#define CM_AROW 144
#define CM_BROW 272

template <bool XF32>
__global__ __launch_bounds__(256, 3) void channel_mix_f16(const void* __restrict__ Xv,
                                                          const __half* __restrict__ thT,
                                                          __half* __restrict__ Y)
{
    __shared__ __half As[96 * (CM_AROW/2)];
    __shared__ __half Bs[64 * (CM_BROW/2)];
    const uint32_t smA = (uint32_t)__cvta_generic_to_shared(As);
    const uint32_t smB = (uint32_t)__cvta_generic_to_shared(Bs);

    const int bt = blockIdx.x;
    const int b  = bt / Tv;
    const int t  = bt % Tv;
    const int m0 = blockIdx.y * 128;
    const int p0 = blockIdx.z * 96;
    const int tid  = threadIdx.x;
    const int wid  = tid >> 5;
    const int lane = tid & 31;
    const int gq = lane >> 2;
    const int tg = lane & 3;
    const int wm = (wid & 1) * 48;       // 2 warps in p
    const int wn = (wid >> 1) * 32;      // 4 warps in m

    // theta half-tile: 96 rows x 128B -> 768 cp16 (3/thread)
    #pragma unroll
    for (int l = 0; l < 3; l++) {
        int slot = tid + 256 * l;
        int p = slot >> 3, q = slot & 7;
        cp16(smA + (uint32_t)(p * CM_AROW + q * 16), thT + (p0 + p) * 64 + q * 8);
    }
    // x tile
    if (XF32) {
        const float* X = (const float*)Xv;
        #pragma unroll
        for (int l = 0; l < 8; l++) {
            int f  = tid + 256 * l;           // 2048 float4 slots
            int i  = f >> 5;
            int mv = (f & 31) * 4;
            float4 v = *reinterpret_cast<const float4*>(
                X + ((size_t)(b * Cv + i) * Tv + t) * Nv + m0 + mv);
            __half* dst = &Bs[i * (CM_BROW/2) + mv];
            *reinterpret_cast<__half2*>(dst)     = __floats2half2_rn(v.x, v.y);
            *reinterpret_cast<__half2*>(dst + 2) = __floats2half2_rn(v.z, v.w);
        }
    } else {
        const __half* X = (const __half*)Xv;
        #pragma unroll
        for (int l = 0; l < 4; l++) {
            int slot = tid + 256 * l;
            int i = slot >> 4, q = slot & 15;
            cp16(smB + (uint32_t)(i * CM_BROW + q * 16),
                 X + ((size_t)(b * Cv + i) * Tv + t) * Nv + m0 + q * 8);
        }
    }
    cp_commit();
    asm volatile("cp.async.wait_group 0;" ::: "memory");
    __syncthreads();

    float acc[3][4][4];
    #pragma unroll
    for (int a = 0; a < 3; a++)
        #pragma unroll
        for (int c = 0; c < 4; c++)
            #pragma unroll
            for (int q = 0; q < 4; q++) acc[a][c][q] = 0.f;

    const int rowA = (lane & 7) + ((lane >> 3) & 1) * 8;
    const int colA = (lane >> 4) * 16;
    const int rowB = (lane & 7) + ((lane >> 3) & 1) * 8;
    const int colB = ((lane >> 4) & 1) * 16;

    #pragma unroll
    for (int ks = 0; ks < 4; ks++) {
        uint32_t af[3][4];
        #pragma unroll
        for (int mt = 0; mt < 3; mt++)
            ldsm_x4(af[mt][0], af[mt][1], af[mt][2], af[mt][3],
                    smA + (uint32_t)((wm + 16*mt + rowA) * CM_AROW + ks * 32 + colA));
        uint32_t bf[4][2];
        #pragma unroll
        for (int ntp = 0; ntp < 2; ntp++)
            ldsm_x4_t(bf[2*ntp][0], bf[2*ntp][1], bf[2*ntp+1][0], bf[2*ntp+1][1],
                      smB + (uint32_t)((ks*16 + rowB) * CM_BROW + (wn + 16*ntp) * 2 + colB));
        #pragma unroll
        for (int mt = 0; mt < 3; mt++)
            #pragma unroll
            for (int nt = 0; nt < 4; nt++)
                mma_f16(acc[mt][nt][0], acc[mt][nt][1], acc[mt][nt][2], acc[mt][nt][3],
                        af[mt][0], af[mt][1], af[mt][2], af[mt][3],
                        bf[nt][0], bf[nt][1]);
    }

    #pragma unroll
    for (int mt = 0; mt < 3; mt++) {
        int p1 = p0 + wm + 16 * mt + gq;
        int p2 = p1 + 8;
        int o1 = p1 / 3, k1 = p1 - o1 * 3;
        int o2 = p2 / 3, k2 = p2 - o2 * 3;
        size_t r1 = ((size_t)(b * Cv + o1) * Tv + t) * (size_t)Kdim + (size_t)k1 * Nv;
        size_t r2 = ((size_t)(b * Cv + o2) * Tv + t) * (size_t)Kdim + (size_t)k2 * Nv;
        #pragma unroll
        for (int nt = 0; nt < 4; nt++) {
            int c = m0 + wn + 8 * nt + 2 * tg;
            *reinterpret_cast<__half2*>(Y + r1 + c) = __floats2half2_rn(acc[mt][nt][0], acc[mt][nt][1]);
            *reinterpret_cast<__half2*>(Y + r2 + c) = __floats2half2_rn(acc[mt][nt][2], acc[mt][nt][3]);
        }
    }
}

// ---------------- kernel C: fp16 mma GEMM, tile 96x128, GBK=64, NSTAGE=3 ----
#define GBM 96
#define GBK 64
#define AROW 144
#define STAGE_ROWS (GBM + 128)
#define STAGE_BYTES (STAGE_ROWS * AROW)
#define NSTAGE 3
#define GSMEM_BYTES (NSTAGE*STAGE_BYTES)

template <bool RF32>
__global__ __launch_bounds__(256, 2) void gemm_f16(const __half* __restrict__ A,
                                                   const __half* __restrict__ Bk,
                                                   const float*  __restrict__ bias,
                                                   const void*   __restrict__ residv,
                                                   __half*       __restrict__ Cout)
{
    extern __shared__ char smem[];
    const uint32_t sbase = (uint32_t)__cvta_generic_to_shared(smem);

    const int bn  = blockIdx.x;
    const int bm  = blockIdx.y;
    const int tid = threadIdx.x;
    const int wid = tid >> 5;
    const int lane = tid & 31;
    const int gq  = lane >> 2;
    const int tg  = lane & 3;
    const int wm  = (wid & 1) * 48;
    const int wn  = (wid >> 1) * 32;

    const __half* Abase = A + (size_t)bm * GBM * Kdim;
    const __half* Bbase = Bk + (size_t)bn * 128 * Nv;

    auto fill_stage = [&](int c) {
        int s = c % NSTAGE;
        const int k  = c >> 4;
        const int m0 = (c & 15) << 6;
        const __half* Asrc = Abase + (size_t)c * GBK;
        const __half* Bsrc = Bbase + ((size_t)k << 20) + m0;
        const uint32_t Asm = sbase + s * STAGE_BYTES;
        const uint32_t Bsm = Asm + GBM * AROW;
        #pragma unroll
        for (int l = 0; l < 7; l++) {
            int slot = tid + 256 * l;
            int row = slot >> 3, q = slot & 7;
            if (row < GBM)
                cp16(Asm + row * AROW + q * 16, Asrc + (size_t)row * Kdim + q * 8);
            else
                cp16(Bsm + (row - GBM) * AROW + q * 16, Bsrc + (size_t)(row - GBM) * Nv + q * 8);
        }
        cp_commit();
    };

    float acc[3][4][4];
    #pragma unroll
    for (int i = 0; i < 3; i++)
        #pragma unroll
        for (int j = 0; j < 4; j++)
            #pragma unroll
            for (int q = 0; q < 4; q++) acc[i][j][q] = 0.f;

    fill_stage(0);
    fill_stage(1);

    const int rowA = (lane & 7) + ((lane >> 3) & 1) * 8;
    const int colA = (lane >> 4) * 16;
    const int rowB = (lane & 7) + ((lane >> 4) & 1) * 8;
    const int colB = ((lane >> 3) & 1) * 16;

    const int NITER = Kdim / GBK;
    for (int it = 0; it < NITER; it++) {
        asm volatile("cp.async.wait_group 1;" ::: "memory");
        __syncthreads();

        if (it + 2 < NITER) fill_stage(it + 2);
        else                cp_commit();

        const uint32_t Acur = sbase + (it % NSTAGE) * STAGE_BYTES;
        const uint32_t Bcur = Acur + GBM * AROW;

        #pragma unroll
        for (int kh = 0; kh < 4; kh++) {
            const int kb = kh * 32;
            uint32_t af[3][4];
            #pragma unroll
            for (int mt = 0; mt < 3; mt++)
                ldsm_x4(af[mt][0], af[mt][1], af[mt][2], af[mt][3],
                        Acur + (uint32_t)((wm + 16*mt + rowA) * AROW + kb + colA));
            uint32_t bf[4][2];
            #pragma unroll
            for (int ntp = 0; ntp < 2; ntp++)
                ldsm_x4(bf[2*ntp][0], bf[2*ntp][1], bf[2*ntp+1][0], bf[2*ntp+1][1],
                        Bcur + (uint32_t)((wn + 16*ntp + rowB) * AROW + kb + colB));
            #pragma unroll
            for (int mt = 0; mt < 3; mt++)
                #pragma unroll
                for (int nt = 0; nt < 4; nt++)
                    mma_f16(acc[mt][nt][0], acc[mt][nt][1], acc[mt][nt][2], acc[mt][nt][3],
                            af[mt][0], af[mt][1], af[mt][2], af[mt][3],
                            bf[nt][0], bf[nt][1]);
        }
    }

    #pragma unroll
    for (int mt = 0; mt < 3; mt++) {
        int r1 = bm * GBM + wm + 16 * mt + gq;
        int r2 = r1 + 8;
        float bv1 = bias[(r1 / Tv) & (Cv - 1)];
        float bv2 = bias[(r2 / Tv) & (Cv - 1)];
        #pragma unroll
        for (int nt = 0; nt < 4; nt++) {
            int c = bn * 128 + wn + 8 * nt + 2 * tg;
            float z10, z11, z20, z21;
            if (RF32) {
                const float* rp = (const float*)residv;
                float2 a = *reinterpret_cast<const float2*>(rp + (size_t)r1 * Nv + c);
                float2 b2_ = *reinterpret_cast<const float2*>(rp + (size_t)r2 * Nv + c);
                z10 = a.x;  z11 = a.y;  z20 = b2_.x; z21 = b2_.y;
            } else {
                const __half* rp = (const __half*)residv;
                __half2 a = *reinterpret_cast<const __half2*>(rp + (size_t)r1 * Nv + c);
                __half2 b2_ = *reinterpret_cast<const __half2*>(rp + (size_t)r2 * Nv + c);
                z10 = __low2float(a);  z11 = __high2float(a);
                z20 = __low2float(b2_); z21 = __high2float(b2_);
            }
            float v0 = fmaxf(acc[mt][nt][0] + bv1 + z10, 0.f);
            float v1 = fmaxf(acc[mt][nt][1] + bv1 + z11, 0.f);
            float v2 = fmaxf(acc[mt][nt][2] + bv2 + z20, 0.f);
            float v3 = fmaxf(acc[mt][nt][3] + bv2 + z21, 0.f);
            *reinterpret_cast<__half2*>(Cout + (size_t)r1 * Nv + c) = __floats2half2_rn(v0, v1);
            *reinterpret_cast<__half2*>(Cout + (size_t)r2 * Nv + c) = __floats2half2_rn(v2, v3);
        }
    }
}

// ---------------- kernel D: final FC via fp16 mma ----------------
#define FC_WROW 144
#define FC_XROW 272

__global__ __launch_bounds__(256, 2) void fc_mma(const __half* __restrict__ X2c,
                                                 const __half* __restrict__ fcwH,
                                                 const float* __restrict__ fcb,
                                                 float*       __restrict__ out)
{
    __shared__ __half Ws[OUTv * (FC_WROW/2)];
    __shared__ __half Xs[Cv * (FC_XROW/2)];
    __shared__ float  bsf[OUTv];
    const uint32_t smW = (uint32_t)__cvta_generic_to_shared(Ws);
    const uint32_t smX = (uint32_t)__cvta_generic_to_shared(Xs);

    const int bt = blockIdx.x;
    const int b  = bt / Tv;
    const int t  = bt % Tv;
    const int n0 = blockIdx.y * 128;
    const int tid  = threadIdx.x;
    const int wid  = tid >> 5;
    const int lane = tid & 31;
    const int gq = lane >> 2;
    const int tg = lane & 3;
    const int wm = (wid & 3) * 32;
    const int wn = (wid >> 2) * 32;

    #pragma unroll
    for (int l = 0; l < 2; l++) {
        int slot = tid + 256 * l;
        int j = slot >> 3, q = slot & 7;
        cp16(smW + (uint32_t)(j * FC_WROW + q * 16), fcwH + j * Cv + q * 8);
    }
    #pragma unroll
    for (int l = 0; l < 4; l++) {
        int slot = tid + 256 * l;
        int o = slot >> 4, q = slot & 15;
        cp16(smX + (uint32_t)(o * FC_XROW + q * 16),
             X2c + ((size_t)(b * Cv + o) * Tv + t) * Nv + n0 + q * 8);
    }
    if (tid < OUTv) bsf[tid] = fcb[tid];
    cp_commit();
    asm volatile("cp.async.wait_group 0;" ::: "memory");
    __syncthreads();

    float acc[2][4][4];
    #pragma unroll
    for (int i = 0; i < 2; i++)
        #pragma unroll
        for (int j = 0; j < 4; j++)
            #pragma unroll
            for (int q = 0; q < 4; q++) acc[i][j][q] = 0.f;

    const int rowAt = (lane & 7) + ((lane >> 4) & 1) * 8;
    const int colAt = ((lane >> 3) & 1) * 16;
    const int rowB = (lane & 7) + ((lane >> 4) & 1) * 8;
    const int colB = ((lane >> 3) & 1) * 16;

    #pragma unroll
    for (int ks = 0; ks < 4; ks++) {
        uint32_t af[2][4];
        #pragma unroll
        for (int mt = 0; mt < 2; mt++)
            ldsm_x4_t(af[mt][0], af[mt][1], af[mt][2], af[mt][3],
                      smX + (uint32_t)((ks*16 + rowAt) * FC_XROW + (wm + 16*mt) * 2 + colAt));
        uint32_t bf[4][2];
        #pragma unroll
        for (int ntp = 0; ntp < 2; ntp++)
            ldsm_x4(bf[2*ntp][0], bf[2*ntp][1], bf[2*ntp+1][0], bf[2*ntp+1][1],
                    smW + (uint32_t)((wn + 16*ntp + rowB) * FC_WROW + ks * 32 + colB));
        #pragma unroll
        for (int mt = 0; mt < 2; mt++)
            #pragma unroll
            for (int nt = 0; nt < 4; nt++)
                mma_f16(acc[mt][nt][0], acc[mt][nt][1], acc[mt][nt][2], acc[mt][nt][3],
                        af[mt][0], af[mt][1], af[mt][2], af[mt][3],
                        bf[nt][0], bf[nt][1]);
    }

    #pragma unroll
    for (int mt = 0; mt < 2; mt++) {
        int nr1 = wm + 16 * mt + gq;
        int nr2 = nr1 + 8;
        size_t o1 = ((size_t)bt * Nv + n0 + nr1) * OUTv;
        size_t o2 = ((size_t)bt * Nv + n0 + nr2) * OUTv;
        #pragma unroll
        for (int nt = 0; nt < 4; nt++) {
            int j = wn + 8 * nt + 2 * tg;
            float bj0 = bsf[j], bj1 = bsf[j + 1];
            float2 v1 = make_float2(acc[mt][nt][0] + bj0, acc[mt][nt][1] + bj1);
            float2 v2 = make_float2(acc[mt][nt][2] + bj0, acc[mt][nt][3] + bj1);
            *reinterpret_cast<float2*>(out + o1 + j) = v1;
            *reinterpret_cast<float2*>(out + o2 + j) = v2;
        }
    }
}

// ---------------- static-init module materialization ----------------
namespace {
struct ModuleLoader {
    ModuleLoader() {
        cudaFree(0);
        cudaGetSymbolAddress((void**)&pLkH, g_LkH);
        cudaGetSymbolAddress((void**)&pYH,  g_YH);
        cudaGetSymbolAddress((void**)&pX1,  g_X1);
        cudaGetSymbolAddress((void**)&pX2,  g_X2);
        cudaGetSymbolAddress((void**)&pTh1, g_Th1);
        cudaGetSymbolAddress((void**)&pTh2, g_Th2);
        cudaGetSymbolAddress((void**)&pFcW, g_FcW);
        cudaMemset(pLkH, 0, 4);
        cudaMemset(pYH,  0, 4);
        cudaMemset(pX1,  0, 4);
        cudaMemset(pX2,  0, 4);
        cudaMemset(pTh1, 0, 4);
        cudaMemset(pTh2, 0, 4);
        cudaMemset(pFcW, 0, 4);
        cudaFuncSetAttribute(gemm_f16<true>,  cudaFuncAttributeMaxDynamicSharedMemorySize, GSMEM_BYTES);
        cudaFuncSetAttribute(gemm_f16<false>, cudaFuncAttributeMaxDynamicSharedMemorySize, GSMEM_BYTES);
        cudaDeviceSynchronize();
    }
};
ModuleLoader g_loader;
}

// ---------------- launch ----------------
extern "C" void kernel_launch(void* const* d_in, const int* in_sizes, int n_in,
                              void* d_out, int out_size)
{
    const float* x      = (const float*)d_in[0];
    const float* Lk     = (const float*)d_in[1];
    const float* theta1 = (const float*)d_in[2];
    const float* b1     = (const float*)d_in[3];
    const float* theta2 = (const float*)d_in[4];
    const float* b2     = (const float*)d_in[5];
    const float* fc_w   = (const float*)d_in[6];
    const float* fc_b   = (const float*)d_in[7];
    float* out = (float*)d_out;

    // 1) prep: Lk + thetas + fcw, one launch
    prep_all<<<3072 + 96 + 1, 256>>>(Lk, theta1, theta2, fc_w, pLkH, pTh1, pTh2, pFcW);

    // 2) layer 1
    channel_mix_f16<true><<<dim3(BT, Nv / 128, 2), 256>>>(x, pTh1, pYH);
    gemm_f16<true><<<dim3(8, Mrows / GBM), 256, GSMEM_BYTES>>>(pYH, pLkH, b1, x, pX1);

    // 3) layer 2
    channel_mix_f16<false><<<dim3(BT, Nv / 128, 2), 256>>>(pX1, pTh2, pYH);
    gemm_f16<false><<<dim3(8, Mrows / GBM), 256, GSMEM_BYTES>>>(pYH, pLkH, b2, pX1, pX2);

    // 4) final FC (fp16 mma)
    fc_mma<<<dim3(BT, Nv / 128), 256>>>(pX2, pFcW, fc_b, out);
}

// round 16
// speedup vs baseline: 1.0090x; 1.0090x over previous
#include <cuda_runtime.h>
#include <cuda_fp16.h>
#include <cstdint>
#include <cstdio>

// Problem constants
#define Bv   32
#define Cv   64
#define Tv   12
#define Nv   1024
#define KSv  3
#define OUTv 64

#define Kdim   (KSv*Nv)        // 3072
#define Mrows  (Bv*Cv*Tv)      // 24576
#define BT     (Bv*Tv)         // 384

// ---------------- scratch ----------------
__device__ __half g_LkH[KSv * Nv * Nv];            // fp16(Lk), natural [k][n][m]
__device__ __half g_YH [(size_t)Mrows * Kdim];     // channel-mix output (fp16)
__device__ __half g_X1 [(size_t)Mrows * Nv];
__device__ __half g_X2 [(size_t)Mrows * Nv];
__device__ __half g_Th1[192 * 64];
__device__ __half g_Th2[192 * 64];
__device__ __half g_FcW[OUTv * Cv];                // fp16(fc_w) [j][o]

static __half *pLkH = nullptr, *pYH = nullptr;
static __half *pX1 = nullptr, *pX2 = nullptr, *pTh1 = nullptr, *pTh2 = nullptr;
static __half *pFcW = nullptr;

// ---- helpers ----
__device__ __forceinline__ void mma_f16(float& c0, float& c1, float& c2, float& c3,
                                        uint32_t a0, uint32_t a1, uint32_t a2, uint32_t a3,
                                        uint32_t b0, uint32_t b1) {
    asm volatile(
        "mma.sync.aligned.m16n8k16.row.col.f32.f16.f16.f32 "
        "{%0,%1,%2,%3}, {%4,%5,%6,%7}, {%8,%9}, {%0,%1,%2,%3};"
        : "+f"(c0), "+f"(c1), "+f"(c2), "+f"(c3)
        : "r"(a0), "r"(a1), "r"(a2), "r"(a3), "r"(b0), "r"(b1));
}

__device__ __forceinline__ void ldsm_x4(uint32_t& r0, uint32_t& r1, uint32_t& r2, uint32_t& r3,
                                        uint32_t addr) {
    asm volatile("ldmatrix.sync.aligned.m8n8.x4.shared.b16 {%0,%1,%2,%3}, [%4];"
                 : "=r"(r0), "=r"(r1), "=r"(r2), "=r"(r3) : "r"(addr));
}
__device__ __forceinline__ void ldsm_x4_t(uint32_t& r0, uint32_t& r1, uint32_t& r2, uint32_t& r3,
                                          uint32_t addr) {
    asm volatile("ldmatrix.sync.aligned.m8n8.x4.trans.shared.b16 {%0,%1,%2,%3}, [%4];"
                 : "=r"(r0), "=r"(r1), "=r"(r2), "=r"(r3) : "r"(addr));
}

__device__ __forceinline__ void cp16(uint32_t dst_smem, const void* src) {
    asm volatile("cp.async.cg.shared.global [%0], [%1], 16;" :: "r"(dst_smem), "l"(src));
}
__device__ __forceinline__ void cp_commit() { asm volatile("cp.async.commit_group;"); }

// ---------------- prep: Lk + thetas + fcw, ONE launch ----------------
__global__ __launch_bounds__(256) void prep_all(const float* __restrict__ Lk,
                                                const float* __restrict__ th1,
                                                const float* __restrict__ th2,
                                                const float* __restrict__ fcw,
                                                __half* __restrict__ LkH,
                                                __half* __restrict__ o1,
                                                __half* __restrict__ o2,
                                                __half* __restrict__ fcwH)
{
    int bid = blockIdx.x;
    if (bid < 3072) {
        size_t i = (size_t)bid * 1024 + threadIdx.x * 4;
        float4 v = *reinterpret_cast<const float4*>(Lk + i);
        *reinterpret_cast<__half2*>(LkH + i)     = __floats2half2_rn(v.x, v.y);
        *reinterpret_cast<__half2*>(LkH + i + 2) = __floats2half2_rn(v.z, v.w);
    } else if (bid < 3168) {
        int b2 = bid - 3072;                 // 0..95
        const float* src = (b2 >= 48) ? th2 : th1;
        __half*      dst = (b2 >= 48) ? o2  : o1;
        int idx = (b2 % 48) * 256 + threadIdx.x;
        int i = idx / 192;
        int p = idx - i * 192;
        dst[p * 64 + i] = __float2half_rn(src[idx]);
    } else {
        for (int i = threadIdx.x; i < OUTv * Cv; i += 256)
            fcwH[i] = __float2half_rn(fcw[i]);
    }
}

// ---------------- kernel B: channel mix, 2 m-blocks per CTA, pipelined ------
#define CM_AROW 144
#define CM_BROW 272
#define CM_SMEM (192*CM_AROW + 2*64*CM_BROW)   // 62464 B

template <bool XF32>
__global__ __launch_bounds__(256, 2) void channel_mix_f16(const void* __restrict__ Xv,
                                                          const __half* __restrict__ thT,
                                                          __half* __restrict__ Y)
{
    extern __shared__ __half cmsm[];
    __half* As = cmsm;                                  // [192][72]
    __half* Bs = cmsm + 192 * (CM_AROW/2);              // [2][64][136]
    const uint32_t smA = (uint32_t)__cvta_generic_to_shared(As);
    const uint32_t smB = (uint32_t)__cvta_generic_to_shared(Bs);

    const int bt = blockIdx.x;
    const int b  = bt / Tv;
    const int t  = bt % Tv;
    const int mb0 = blockIdx.y * 2;       // first of two m-blocks
    const int tid  = threadIdx.x;
    const int wid  = tid >> 5;
    const int lane = tid & 31;
    const int gq = lane >> 2;
    const int tg = lane & 3;
    const int wm = (wid & 3) * 48;
    const int wn = (wid >> 2) * 64;

    if (XF32) {
        // layer 1: fp32 x -> LDGs first (start latency early), then theta cp.async
        const float* X = (const float*)Xv;
        float4 xr[2][8];
        #pragma unroll
        for (int mb = 0; mb < 2; mb++) {
            int m0 = (mb0 + mb) * 128;
            #pragma unroll
            for (int l = 0; l < 8; l++) {
                int f  = tid + 256 * l;
                int i  = f >> 5;
                int mv = (f & 31) * 4;
                xr[mb][l] = *reinterpret_cast<const float4*>(
                    X + ((size_t)(b * Cv + i) * Tv + t) * Nv + m0 + mv);
            }
        }
        #pragma unroll
        for (int l = 0; l < 6; l++) {
            int slot = tid + 256 * l;
            int p = slot >> 3, q = slot & 7;
            cp16(smA + (uint32_t)(p * CM_AROW + q * 16), thT + p * 64 + q * 8);
        }
        cp_commit();
        #pragma unroll
        for (int mb = 0; mb < 2; mb++) {
            __half* Bsl = Bs + mb * 64 * (CM_BROW/2);
            #pragma unroll
            for (int l = 0; l < 8; l++) {
                int f  = tid + 256 * l;
                int i  = f >> 5;
                int mv = (f & 31) * 4;
                float4 v = xr[mb][l];
                __half* dst = &Bsl[i * (CM_BROW/2) + mv];
                *reinterpret_cast<__half2*>(dst)     = __floats2half2_rn(v.x, v.y);
                *reinterpret_cast<__half2*>(dst + 2) = __floats2half2_rn(v.z, v.w);
            }
        }
        asm volatile("cp.async.wait_group 0;" ::: "memory");
        __syncthreads();
    } else {
        // layer 2: fp16 input, pipelined groups
        const __half* X = (const __half*)Xv;
        // group 0: theta + X tile mb0
        #pragma unroll
        for (int l = 0; l < 6; l++) {
            int slot = tid + 256 * l;
            int p = slot >> 3, q = slot & 7;
            cp16(smA + (uint32_t)(p * CM_AROW + q * 16), thT + p * 64 + q * 8);
        }
        {
            int m0 = mb0 * 128;
            #pragma unroll
            for (int l = 0; l < 4; l++) {
                int slot = tid + 256 * l;
                int i = slot >> 4, q = slot & 15;
                cp16(smB + (uint32_t)(i * CM_BROW + q * 16),
                     X + ((size_t)(b * Cv + i) * Tv + t) * Nv + m0 + q * 8);
            }
        }
        cp_commit();
        // group 1: X tile mb1
        {
            int m0 = (mb0 + 1) * 128;
            uint32_t Bsl = smB + 64 * CM_BROW;
            #pragma unroll
            for (int l = 0; l < 4; l++) {
                int slot = tid + 256 * l;
                int i = slot >> 4, q = slot & 15;
                cp16(Bsl + (uint32_t)(i * CM_BROW + q * 16),
                     X + ((size_t)(b * Cv + i) * Tv + t) * Nv + m0 + q * 8);
            }
        }
        cp_commit();
        asm volatile("cp.async.wait_group 1;" ::: "memory");
        __syncthreads();
    }

    const int rowA = (lane & 7) + ((lane >> 3) & 1) * 8;
    const int colA = (lane >> 4) * 16;
    const int rowB = (lane & 7) + ((lane >> 3) & 1) * 8;
    const int colB = ((lane >> 4) & 1) * 16;

    for (int mb = 0; mb < 2; mb++) {
        const int m0 = (mb0 + mb) * 128;
        const uint32_t Bsl = smB + mb * 64 * CM_BROW;

        float acc[3][8][4];
        #pragma unroll
        for (int a = 0; a < 3; a++)
            #pragma unroll
            for (int c = 0; c < 8; c++)
                #pragma unroll
                for (int q = 0; q < 4; q++) acc[a][c][q] = 0.f;

        #pragma unroll
        for (int ks = 0; ks < 4; ks++) {
            uint32_t af[3][4];
            #pragma unroll
            for (int mt = 0; mt < 3; mt++)
                ldsm_x4(af[mt][0], af[mt][1], af[mt][2], af[mt][3],
                        smA + (uint32_t)((wm + 16*mt + rowA) * CM_AROW + ks * 32 + colA));
            uint32_t bf[8][2];
            #pragma unroll
            for (int ntp = 0; ntp < 4; ntp++)
                ldsm_x4_t(bf[2*ntp][0], bf[2*ntp][1], bf[2*ntp+1][0], bf[2*ntp+1][1],
                          Bsl + (uint32_t)((ks*16 + rowB) * CM_BROW + (wn + 16*ntp) * 2 + colB));
            #pragma unroll
            for (int mt = 0; mt < 3; mt++)
                #pragma unroll
                for (int nt = 0; nt < 8; nt++)
                    mma_f16(acc[mt][nt][0], acc[mt][nt][1], acc[mt][nt][2], acc[mt][nt][3],
                            af[mt][0], af[mt][1], af[mt][2], af[mt][3],
                            bf[nt][0], bf[nt][1]);
        }

        #pragma unroll
        for (int mt = 0; mt < 3; mt++) {
            int p1 = wm + 16 * mt + gq;
            int p2 = p1 + 8;
            int o1 = p1 / 3, k1 = p1 - o1 * 3;
            int o2 = p2 / 3, k2 = p2 - o2 * 3;
            size_t r1 = ((size_t)(b * Cv + o1) * Tv + t) * (size_t)Kdim + (size_t)k1 * Nv;
            size_t r2 = ((size_t)(b * Cv + o2) * Tv + t) * (size_t)Kdim + (size_t)k2 * Nv;
            #pragma unroll
            for (int nt = 0; nt < 8; nt++) {
                int c = m0 + wn + 8 * nt + 2 * tg;
                *reinterpret_cast<__half2*>(Y + r1 + c) = __floats2half2_rn(acc[mt][nt][0], acc[mt][nt][1]);
                *reinterpret_cast<__half2*>(Y + r2 + c) = __floats2half2_rn(acc[mt][nt][2], acc[mt][nt][3]);
            }
        }

        if (!XF32 && mb == 0) {
            asm volatile("cp.async.wait_group 0;" ::: "memory");
            __syncthreads();
        }
    }
}

// ---------------- kernel C: fp16 mma GEMM, tile 96x128, GBK=64, NSTAGE=3 ----
#define GBM 96
#define GBK 64
#define AROW 144
#define STAGE_ROWS (GBM + 128)
#define STAGE_BYTES (STAGE_ROWS * AROW)
#define NSTAGE 3
#define GSMEM_BYTES (NSTAGE*STAGE_BYTES)

template <bool RF32>
__global__ __launch_bounds__(256, 2) void gemm_f16(const __half* __restrict__ A,
                                                   const __half* __restrict__ Bk,
                                                   const float*  __restrict__ bias,
                                                   const void*   __restrict__ residv,
                                                   __half*       __restrict__ Cout)
{
    extern __shared__ char smem[];
    const uint32_t sbase = (uint32_t)__cvta_generic_to_shared(smem);

    const int bn  = blockIdx.x;
    const int bm  = blockIdx.y;
    const int tid = threadIdx.x;
    const int wid = tid >> 5;
    const int lane = tid & 31;
    const int gq  = lane >> 2;
    const int tg  = lane & 3;
    const int wm  = (wid & 1) * 48;
    const int wn  = (wid >> 1) * 32;

    const __half* Abase = A + (size_t)bm * GBM * Kdim;
    const __half* Bbase = Bk + (size_t)bn * 128 * Nv;

    auto fill_stage = [&](int c) {
        int s = c % NSTAGE;
        const int k  = c >> 4;
        const int m0 = (c & 15) << 6;
        const __half* Asrc = Abase + (size_t)c * GBK;
        const __half* Bsrc = Bbase + ((size_t)k << 20) + m0;
        const uint32_t Asm = sbase + s * STAGE_BYTES;
        const uint32_t Bsm = Asm + GBM * AROW;
        #pragma unroll
        for (int l = 0; l < 7; l++) {
            int slot = tid + 256 * l;
            int row = slot >> 3, q = slot & 7;
            if (row < GBM)
                cp16(Asm + row * AROW + q * 16, Asrc + (size_t)row * Kdim + q * 8);
            else
                cp16(Bsm + (row - GBM) * AROW + q * 16, Bsrc + (size_t)(row - GBM) * Nv + q * 8);
        }
        cp_commit();
    };

    float acc[3][4][4];
    #pragma unroll
    for (int i = 0; i < 3; i++)
        #pragma unroll
        for (int j = 0; j < 4; j++)
            #pragma unroll
            for (int q = 0; q < 4; q++) acc[i][j][q] = 0.f;

    fill_stage(0);
    fill_stage(1);

    const int rowA = (lane & 7) + ((lane >> 3) & 1) * 8;
    const int colA = (lane >> 4) * 16;
    const int rowB = (lane & 7) + ((lane >> 4) & 1) * 8;
    const int colB = ((lane >> 3) & 1) * 16;

    const int NITER = Kdim / GBK;
    for (int it = 0; it < NITER; it++) {
        asm volatile("cp.async.wait_group 1;" ::: "memory");
        __syncthreads();

        if (it + 2 < NITER) fill_stage(it + 2);
        else                cp_commit();

        const uint32_t Acur = sbase + (it % NSTAGE) * STAGE_BYTES;
        const uint32_t Bcur = Acur + GBM * AROW;

        #pragma unroll
        for (int kh = 0; kh < 4; kh++) {
            const int kb = kh * 32;
            uint32_t af[3][4];
            #pragma unroll
            for (int mt = 0; mt < 3; mt++)
                ldsm_x4(af[mt][0], af[mt][1], af[mt][2], af[mt][3],
                        Acur + (uint32_t)((wm + 16*mt + rowA) * AROW + kb + colA));
            uint32_t bf[4][2];
            #pragma unroll
            for (int ntp = 0; ntp < 2; ntp++)
                ldsm_x4(bf[2*ntp][0], bf[2*ntp][1], bf[2*ntp+1][0], bf[2*ntp+1][1],
                        Bcur + (uint32_t)((wn + 16*ntp + rowB) * AROW + kb + colB));
            #pragma unroll
            for (int mt = 0; mt < 3; mt++)
                #pragma unroll
                for (int nt = 0; nt < 4; nt++)
                    mma_f16(acc[mt][nt][0], acc[mt][nt][1], acc[mt][nt][2], acc[mt][nt][3],
                            af[mt][0], af[mt][1], af[mt][2], af[mt][3],
                            bf[nt][0], bf[nt][1]);
        }
    }

    #pragma unroll
    for (int mt = 0; mt < 3; mt++) {
        int r1 = bm * GBM + wm + 16 * mt + gq;
        int r2 = r1 + 8;
        float bv1 = bias[(r1 / Tv) & (Cv - 1)];
        float bv2 = bias[(r2 / Tv) & (Cv - 1)];
        #pragma unroll
        for (int nt = 0; nt < 4; nt++) {
            int c = bn * 128 + wn + 8 * nt + 2 * tg;
            float z10, z11, z20, z21;
            if (RF32) {
                const float* rp = (const float*)residv;
                float2 a = *reinterpret_cast<const float2*>(rp + (size_t)r1 * Nv + c);
                float2 b2_ = *reinterpret_cast<const float2*>(rp + (size_t)r2 * Nv + c);
                z10 = a.x;  z11 = a.y;  z20 = b2_.x; z21 = b2_.y;
            } else {
                const __half* rp = (const __half*)residv;
                __half2 a = *reinterpret_cast<const __half2*>(rp + (size_t)r1 * Nv + c);
                __half2 b2_ = *reinterpret_cast<const __half2*>(rp + (size_t)r2 * Nv + c);
                z10 = __low2float(a);  z11 = __high2float(a);
                z20 = __low2float(b2_); z21 = __high2float(b2_);
            }
            float v0 = fmaxf(acc[mt][nt][0] + bv1 + z10, 0.f);
            float v1 = fmaxf(acc[mt][nt][1] + bv1 + z11, 0.f);
            float v2 = fmaxf(acc[mt][nt][2] + bv2 + z20, 0.f);
            float v3 = fmaxf(acc[mt][nt][3] + bv2 + z21, 0.f);
            *reinterpret_cast<__half2*>(Cout + (size_t)r1 * Nv + c) = __floats2half2_rn(v0, v1);
            *reinterpret_cast<__half2*>(Cout + (size_t)r2 * Nv + c) = __floats2half2_rn(v2, v3);
        }
    }
}

// ---------------- kernel D: final FC via fp16 mma ----------------
#define FC_WROW 144
#define FC_XROW 272

__global__ __launch_bounds__(256, 2) void fc_mma(const __half* __restrict__ X2c,
                                                 const __half* __restrict__ fcwH,
                                                 const float* __restrict__ fcb,
                                                 float*       __restrict__ out)
{
    __shared__ __half Ws[OUTv * (FC_WROW/2)];
    __shared__ __half Xs[Cv * (FC_XROW/2)];
    __shared__ float  bsf[OUTv];
    const uint32_t smW = (uint32_t)__cvta_generic_to_shared(Ws);
    const uint32_t smX = (uint32_t)__cvta_generic_to_shared(Xs);

    const int bt = blockIdx.x;
    const int b  = bt / Tv;
    const int t  = bt % Tv;
    const int n0 = blockIdx.y * 128;
    const int tid  = threadIdx.x;
    const int wid  = tid >> 5;
    const int lane = tid & 31;
    const int gq = lane >> 2;
    const int tg = lane & 3;
    const int wm = (wid & 3) * 32;
    const int wn = (wid >> 2) * 32;

    #pragma unroll
    for (int l = 0; l < 2; l++) {
        int slot = tid + 256 * l;
        int j = slot >> 3, q = slot & 7;
        cp16(smW + (uint32_t)(j * FC_WROW + q * 16), fcwH + j * Cv + q * 8);
    }
    #pragma unroll
    for (int l = 0; l < 4; l++) {
        int slot = tid + 256 * l;
        int o = slot >> 4, q = slot & 15;
        cp16(smX + (uint32_t)(o * FC_XROW + q * 16),
             X2c + ((size_t)(b * Cv + o) * Tv + t) * Nv + n0 + q * 8);
    }
    if (tid < OUTv) bsf[tid] = fcb[tid];
    cp_commit();
    asm volatile("cp.async.wait_group 0;" ::: "memory");
    __syncthreads();

    float acc[2][4][4];
    #pragma unroll
    for (int i = 0; i < 2; i++)
        #pragma unroll
        for (int j = 0; j < 4; j++)
            #pragma unroll
            for (int q = 0; q < 4; q++) acc[i][j][q] = 0.f;

    const int rowAt = (lane & 7) + ((lane >> 4) & 1) * 8;
    const int colAt = ((lane >> 3) & 1) * 16;
    const int rowB = (lane & 7) + ((lane >> 4) & 1) * 8;
    const int colB = ((lane >> 3) & 1) * 16;

    #pragma unroll
    for (int ks = 0; ks < 4; ks++) {
        uint32_t af[2][4];
        #pragma unroll
        for (int mt = 0; mt < 2; mt++)
            ldsm_x4_t(af[mt][0], af[mt][1], af[mt][2], af[mt][3],
                      smX + (uint32_t)((ks*16 + rowAt) * FC_XROW + (wm + 16*mt) * 2 + colAt));
        uint32_t bf[4][2];
        #pragma unroll
        for (int ntp = 0; ntp < 2; ntp++)
            ldsm_x4(bf[2*ntp][0], bf[2*ntp][1], bf[2*ntp+1][0], bf[2*ntp+1][1],
                    smW + (uint32_t)((wn + 16*ntp + rowB) * FC_WROW + ks * 32 + colB));
        #pragma unroll
        for (int mt = 0; mt < 2; mt++)
            #pragma unroll
            for (int nt = 0; nt < 4; nt++)
                mma_f16(acc[mt][nt][0], acc[mt][nt][1], acc[mt][nt][2], acc[mt][nt][3],
                        af[mt][0], af[mt][1], af[mt][2], af[mt][3],
                        bf[nt][0], bf[nt][1]);
    }

    #pragma unroll
    for (int mt = 0; mt < 2; mt++) {
        int nr1 = wm + 16 * mt + gq;
        int nr2 = nr1 + 8;
        size_t o1 = ((size_t)bt * Nv + n0 + nr1) * OUTv;
        size_t o2 = ((size_t)bt * Nv + n0 + nr2) * OUTv;
        #pragma unroll
        for (int nt = 0; nt < 4; nt++) {
            int j = wn + 8 * nt + 2 * tg;
            float bj0 = bsf[j], bj1 = bsf[j + 1];
            float2 v1 = make_float2(acc[mt][nt][0] + bj0, acc[mt][nt][1] + bj1);
            float2 v2 = make_float2(acc[mt][nt][2] + bj0, acc[mt][nt][3] + bj1);
            *reinterpret_cast<float2*>(out + o1 + j) = v1;
            *reinterpret_cast<float2*>(out + o2 + j) = v2;
        }
    }
}

// ---------------- static-init module materialization ----------------
namespace {
struct ModuleLoader {
    ModuleLoader() {
        cudaFree(0);
        cudaGetSymbolAddress((void**)&pLkH, g_LkH);
        cudaGetSymbolAddress((void**)&pYH,  g_YH);
        cudaGetSymbolAddress((void**)&pX1,  g_X1);
        cudaGetSymbolAddress((void**)&pX2,  g_X2);
        cudaGetSymbolAddress((void**)&pTh1, g_Th1);
        cudaGetSymbolAddress((void**)&pTh2, g_Th2);
        cudaGetSymbolAddress((void**)&pFcW, g_FcW);
        cudaMemset(pLkH, 0, 4);
        cudaMemset(pYH,  0, 4);
        cudaMemset(pX1,  0, 4);
        cudaMemset(pX2,  0, 4);
        cudaMemset(pTh1, 0, 4);
        cudaMemset(pTh2, 0, 4);
        cudaMemset(pFcW, 0, 4);
        cudaFuncSetAttribute(gemm_f16<true>,  cudaFuncAttributeMaxDynamicSharedMemorySize, GSMEM_BYTES);
        cudaFuncSetAttribute(gemm_f16<false>, cudaFuncAttributeMaxDynamicSharedMemorySize, GSMEM_BYTES);
        cudaFuncSetAttribute(channel_mix_f16<true>,  cudaFuncAttributeMaxDynamicSharedMemorySize, CM_SMEM);
        cudaFuncSetAttribute(channel_mix_f16<false>, cudaFuncAttributeMaxDynamicSharedMemorySize, CM_SMEM);
        cudaDeviceSynchronize();
    }
};
ModuleLoader g_loader;
}

// ---------------- launch ----------------
extern "C" void kernel_launch(void* const* d_in, const int* in_sizes, int n_in,
                              void* d_out, int out_size)
{
    const float* x      = (const float*)d_in[0];
    const float* Lk     = (const float*)d_in[1];
    const float* theta1 = (const float*)d_in[2];
    const float* b1     = (const float*)d_in[3];
    const float* theta2 = (const float*)d_in[4];
    const float* b2     = (const float*)d_in[5];
    const float* fc_w   = (const float*)d_in[6];
    const float* fc_b   = (const float*)d_in[7];
    float* out = (float*)d_out;

    // 1) prep: Lk + thetas + fcw, one launch
    prep_all<<<3072 + 96 + 1, 256>>>(Lk, theta1, theta2, fc_w, pLkH, pTh1, pTh2, pFcW);

    // 2) layer 1
    channel_mix_f16<true><<<dim3(BT, Nv / 256), 256, CM_SMEM>>>(x, pTh1, pYH);
    gemm_f16<true><<<dim3(8, Mrows / GBM), 256, GSMEM_BYTES>>>(pYH, pLkH, b1, x, pX1);

    // 3) layer 2
    channel_mix_f16<false><<<dim3(BT, Nv / 256), 256, CM_SMEM>>>(pX1, pTh2, pYH);
    gemm_f16<false><<<dim3(8, Mrows / GBM), 256, GSMEM_BYTES>>>(pYH, pLkH, b2, pX1, pX2);

    // 4) final FC (fp16 mma)
    fc_mma<<<dim3(BT, Nv / 128), 256>>>(pX2, pFcW, fc_b, out);
}

// round 17
// speedup vs baseline: 1.0468x; 1.0375x over previous
#include <cuda_runtime.h>
#include <cuda_fp16.h>
#include <cstdint>
#include <cstdio>

// Problem constants
#define Bv   32
#define Cv   64
#define Tv   12
#define Nv   1024
#define KSv  3
#define OUTv 64

#define Kdim   (KSv*Nv)        // 3072
#define Mrows  (Bv*Cv*Tv)      // 24576
#define BT     (Bv*Tv)         // 384

#define NCHUNK 2
#define CROWS  (Mrows/NCHUNK)  // 12288 rows per chunk
#define CBT    (BT/NCHUNK)     // 192 bt per chunk

// ---------------- scratch ----------------
__device__ __half g_LkH[KSv * Nv * Nv];
__device__ __half g_YH [(size_t)Mrows * Kdim];
__device__ __half g_X1 [(size_t)Mrows * Nv];
__device__ __half g_X2 [(size_t)Mrows * Nv];
__device__ __half g_Th1[192 * 64];
__device__ __half g_Th2[192 * 64];
__device__ __half g_FcW[OUTv * Cv];

static __half *pLkH = nullptr, *pYH = nullptr;
static __half *pX1 = nullptr, *pX2 = nullptr, *pTh1 = nullptr, *pTh2 = nullptr;
static __half *pFcW = nullptr;
static cudaStream_t g_str[NCHUNK];
static cudaEvent_t  g_evP, g_evD[NCHUNK];

// ---- helpers ----
__device__ __forceinline__ void mma_f16(float& c0, float& c1, float& c2, float& c3,
                                        uint32_t a0, uint32_t a1, uint32_t a2, uint32_t a3,
                                        uint32_t b0, uint32_t b1) {
    asm volatile(
        "mma.sync.aligned.m16n8k16.row.col.f32.f16.f16.f32 "
        "{%0,%1,%2,%3}, {%4,%5,%6,%7}, {%8,%9}, {%0,%1,%2,%3};"
        : "+f"(c0), "+f"(c1), "+f"(c2), "+f"(c3)
        : "r"(a0), "r"(a1), "r"(a2), "r"(a3), "r"(b0), "r"(b1));
}

__device__ __forceinline__ void ldsm_x4(uint32_t& r0, uint32_t& r1, uint32_t& r2, uint32_t& r3,
                                        uint32_t addr) {
    asm volatile("ldmatrix.sync.aligned.m8n8.x4.shared.b16 {%0,%1,%2,%3}, [%4];"
                 : "=r"(r0), "=r"(r1), "=r"(r2), "=r"(r3) : "r"(addr));
}
__device__ __forceinline__ void ldsm_x4_t(uint32_t& r0, uint32_t& r1, uint32_t& r2, uint32_t& r3,
                                          uint32_t addr) {
    asm volatile("ldmatrix.sync.aligned.m8n8.x4.trans.shared.b16 {%0,%1,%2,%3}, [%4];"
                 : "=r"(r0), "=r"(r1), "=r"(r2), "=r"(r3) : "r"(addr));
}

__device__ __forceinline__ void cp16(uint32_t dst_smem, const void* src) {
    asm volatile("cp.async.cg.shared.global [%0], [%1], 16;" :: "r"(dst_smem), "l"(src));
}
__device__ __forceinline__ void cp_commit() { asm volatile("cp.async.commit_group;"); }

// ---------------- prep: Lk + thetas + fcw, ONE launch ----------------
__global__ __launch_bounds__(256) void prep_all(const float* __restrict__ Lk,
                                                const float* __restrict__ th1,
                                                const float* __restrict__ th2,
                                                const float* __restrict__ fcw,
                                                __half* __restrict__ LkH,
                                                __half* __restrict__ o1,
                                                __half* __restrict__ o2,
                                                __half* __restrict__ fcwH)
{
    int bid = blockIdx.x;
    if (bid < 3072) {
        size_t i = (size_t)bid * 1024 + threadIdx.x * 4;
        float4 v = *reinterpret_cast<const float4*>(Lk + i);
        *reinterpret_cast<__half2*>(LkH + i)     = __floats2half2_rn(v.x, v.y);
        *reinterpret_cast<__half2*>(LkH + i + 2) = __floats2half2_rn(v.z, v.w);
    } else if (bid < 3168) {
        int b2 = bid - 3072;
        const float* src = (b2 >= 48) ? th2 : th1;
        __half*      dst = (b2 >= 48) ? o2  : o1;
        int idx = (b2 % 48) * 256 + threadIdx.x;
        int i = idx / 192;
        int p = idx - i * 192;
        dst[p * 64 + i] = __float2half_rn(src[idx]);
    } else {
        for (int i = threadIdx.x; i < OUTv * Cv; i += 256)
            fcwH[i] = __float2half_rn(fcw[i]);
    }
}

// ---------------- kernel B: channel mix, 2 m-blocks per CTA (R14 proven) ----
#define CM_AROW 144
#define CM_BROW 272
#define CM_SMEM (192*CM_AROW + 2*64*CM_BROW)   // 62464 B

template <bool XF32>
__global__ __launch_bounds__(256, 2) void channel_mix_f16(const void* __restrict__ Xv,
                                                          const __half* __restrict__ thT,
                                                          __half* __restrict__ Y)
{
    extern __shared__ __half cmsm[];
    __half* As = cmsm;
    __half* Bs = cmsm + 192 * (CM_AROW/2);
    const uint32_t smA = (uint32_t)__cvta_generic_to_shared(As);
    const uint32_t smB = (uint32_t)__cvta_generic_to_shared(Bs);

    const int bt = blockIdx.x;            // local to chunk
    const int b  = bt / Tv;
    const int t  = bt % Tv;
    const int mb0 = blockIdx.y * 2;
    const int tid  = threadIdx.x;
    const int wid  = tid >> 5;
    const int lane = tid & 31;
    const int gq = lane >> 2;
    const int tg = lane & 3;
    const int wm = (wid & 3) * 48;
    const int wn = (wid >> 2) * 64;

    #pragma unroll
    for (int l = 0; l < 6; l++) {
        int slot = tid + 256 * l;
        int p = slot >> 3, q = slot & 7;
        cp16(smA + (uint32_t)(p * CM_AROW + q * 16), thT + p * 64 + q * 8);
    }
    if (XF32) {
        const float* X = (const float*)Xv;
        #pragma unroll
        for (int mb = 0; mb < 2; mb++) {
            int m0 = (mb0 + mb) * 128;
            __half* Bsl = Bs + mb * 64 * (CM_BROW/2);
            #pragma unroll
            for (int l = 0; l < 8; l++) {
                int f  = tid + 256 * l;
                int i  = f >> 5;
                int mv = (f & 31) * 4;
                float4 v = *reinterpret_cast<const float4*>(
                    X + ((size_t)(b * Cv + i) * Tv + t) * Nv + m0 + mv);
                __half* dst = &Bsl[i * (CM_BROW/2) + mv];
                *reinterpret_cast<__half2*>(dst)     = __floats2half2_rn(v.x, v.y);
                *reinterpret_cast<__half2*>(dst + 2) = __floats2half2_rn(v.z, v.w);
            }
        }
    } else {
        const __half* X = (const __half*)Xv;
        #pragma unroll
        for (int mb = 0; mb < 2; mb++) {
            int m0 = (mb0 + mb) * 128;
            uint32_t Bsl = smB + mb * 64 * CM_BROW;
            #pragma unroll
            for (int l = 0; l < 4; l++) {
                int slot = tid + 256 * l;
                int i = slot >> 4, q = slot & 15;
                cp16(Bsl + (uint32_t)(i * CM_BROW + q * 16),
                     X + ((size_t)(b * Cv + i) * Tv + t) * Nv + m0 + q * 8);
            }
        }
    }
    cp_commit();
    asm volatile("cp.async.wait_group 0;" ::: "memory");
    __syncthreads();

    const int rowA = (lane & 7) + ((lane >> 3) & 1) * 8;
    const int colA = (lane >> 4) * 16;
    const int rowB = (lane & 7) + ((lane >> 3) & 1) * 8;
    const int colB = ((lane >> 4) & 1) * 16;

    for (int mb = 0; mb < 2; mb++) {
        const int m0 = (mb0 + mb) * 128;
        const uint32_t Bsl = smB + mb * 64 * CM_BROW;

        float acc[3][8][4];
        #pragma unroll
        for (int a = 0; a < 3; a++)
            #pragma unroll
            for (int c = 0; c < 8; c++)
                #pragma unroll
                for (int q = 0; q < 4; q++) acc[a][c][q] = 0.f;

        #pragma unroll
        for (int ks = 0; ks < 4; ks++) {
            uint32_t af[3][4];
            #pragma unroll
            for (int mt = 0; mt < 3; mt++)
                ldsm_x4(af[mt][0], af[mt][1], af[mt][2], af[mt][3],
                        smA + (uint32_t)((wm + 16*mt + rowA) * CM_AROW + ks * 32 + colA));
            uint32_t bf[8][2];
            #pragma unroll
            for (int ntp = 0; ntp < 4; ntp++)
                ldsm_x4_t(bf[2*ntp][0], bf[2*ntp][1], bf[2*ntp+1][0], bf[2*ntp+1][1],
                          Bsl + (uint32_t)((ks*16 + rowB) * CM_BROW + (wn + 16*ntp) * 2 + colB));
            #pragma unroll
            for (int mt = 0; mt < 3; mt++)
                #pragma unroll
                for (int nt = 0; nt < 8; nt++)
                    mma_f16(acc[mt][nt][0], acc[mt][nt][1], acc[mt][nt][2], acc[mt][nt][3],
                            af[mt][0], af[mt][1], af[mt][2], af[mt][3],
                            bf[nt][0], bf[nt][1]);
        }

        #pragma unroll
        for (int mt = 0; mt < 3; mt++) {
            int p1 = wm + 16 * mt + gq;
            int p2 = p1 + 8;
            int o1 = p1 / 3, k1 = p1 - o1 * 3;
            int o2 = p2 / 3, k2 = p2 - o2 * 3;
            size_t r1 = ((size_t)(b * Cv + o1) * Tv + t) * (size_t)Kdim + (size_t)k1 * Nv;
            size_t r2 = ((size_t)(b * Cv + o2) * Tv + t) * (size_t)Kdim + (size_t)k2 * Nv;
            #pragma unroll
            for (int nt = 0; nt < 8; nt++) {
                int c = m0 + wn + 8 * nt + 2 * tg;
                *reinterpret_cast<__half2*>(Y + r1 + c) = __floats2half2_rn(acc[mt][nt][0], acc[mt][nt][1]);
                *reinterpret_cast<__half2*>(Y + r2 + c) = __floats2half2_rn(acc[mt][nt][2], acc[mt][nt][3]);
            }
        }
    }
}

// ---------------- kernel C: fp16 mma GEMM, tile 96x128, GBK=64, NSTAGE=3 ----
#define GBM 96
#define GBK 64
#define AROW 144
#define STAGE_ROWS (GBM + 128)
#define STAGE_BYTES (STAGE_ROWS * AROW)
#define NSTAGE 3
#define GSMEM_BYTES (NSTAGE*STAGE_BYTES)

template <bool RF32>
__global__ __launch_bounds__(256, 2) void gemm_f16(const __half* __restrict__ A,
                                                   const __half* __restrict__ Bk,
                                                   const float*  __restrict__ bias,
                                                   const void*   __restrict__ residv,
                                                   __half*       __restrict__ Cout)
{
    extern __shared__ char smem[];
    const uint32_t sbase = (uint32_t)__cvta_generic_to_shared(smem);

    const int bn  = blockIdx.x;
    const int bm  = blockIdx.y;
    const int tid = threadIdx.x;
    const int wid = tid >> 5;
    const int lane = tid & 31;
    const int gq  = lane >> 2;
    const int tg  = lane & 3;
    const int wm  = (wid & 1) * 48;
    const int wn  = (wid >> 1) * 32;

    const __half* Abase = A + (size_t)bm * GBM * Kdim;
    const __half* Bbase = Bk + (size_t)bn * 128 * Nv;

    auto fill_stage = [&](int c) {
        int s = c % NSTAGE;
        const int k  = c >> 4;
        const int m0 = (c & 15) << 6;
        const __half* Asrc = Abase + (size_t)c * GBK;
        const __half* Bsrc = Bbase + ((size_t)k << 20) + m0;
        const uint32_t Asm = sbase + s * STAGE_BYTES;
        const uint32_t Bsm = Asm + GBM * AROW;
        #pragma unroll
        for (int l = 0; l < 7; l++) {
            int slot = tid + 256 * l;
            int row = slot >> 3, q = slot & 7;
            if (row < GBM)
                cp16(Asm + row * AROW + q * 16, Asrc + (size_t)row * Kdim + q * 8);
            else
                cp16(Bsm + (row - GBM) * AROW + q * 16, Bsrc + (size_t)(row - GBM) * Nv + q * 8);
        }
        cp_commit();
    };

    float acc[3][4][4];
    #pragma unroll
    for (int i = 0; i < 3; i++)
        #pragma unroll
        for (int j = 0; j < 4; j++)
            #pragma unroll
            for (int q = 0; q < 4; q++) acc[i][j][q] = 0.f;

    fill_stage(0);
    fill_stage(1);

    const int rowA = (lane & 7) + ((lane >> 3) & 1) * 8;
    const int colA = (lane >> 4) * 16;
    const int rowB = (lane & 7) + ((lane >> 4) & 1) * 8;
    const int colB = ((lane >> 3) & 1) * 16;

    const int NITER = Kdim / GBK;
    for (int it = 0; it < NITER; it++) {
        asm volatile("cp.async.wait_group 1;" ::: "memory");
        __syncthreads();

        if (it + 2 < NITER) fill_stage(it + 2);
        else                cp_commit();

        const uint32_t Acur = sbase + (it % NSTAGE) * STAGE_BYTES;
        const uint32_t Bcur = Acur + GBM * AROW;

        #pragma unroll
        for (int kh = 0; kh < 4; kh++) {
            const int kb = kh * 32;
            uint32_t af[3][4];
            #pragma unroll
            for (int mt = 0; mt < 3; mt++)
                ldsm_x4(af[mt][0], af[mt][1], af[mt][2], af[mt][3],
                        Acur + (uint32_t)((wm + 16*mt + rowA) * AROW + kb + colA));
            uint32_t bf[4][2];
            #pragma unroll
            for (int ntp = 0; ntp < 2; ntp++)
                ldsm_x4(bf[2*ntp][0], bf[2*ntp][1], bf[2*ntp+1][0], bf[2*ntp+1][1],
                        Bcur + (uint32_t)((wn + 16*ntp + rowB) * AROW + kb + colB));
            #pragma unroll
            for (int mt = 0; mt < 3; mt++)
                #pragma unroll
                for (int nt = 0; nt < 4; nt++)
                    mma_f16(acc[mt][nt][0], acc[mt][nt][1], acc[mt][nt][2], acc[mt][nt][3],
                            af[mt][0], af[mt][1], af[mt][2], af[mt][3],
                            bf[nt][0], bf[nt][1]);
        }
    }

    #pragma unroll
    for (int mt = 0; mt < 3; mt++) {
        int r1 = bm * GBM + wm + 16 * mt + gq;
        int r2 = r1 + 8;
        float bv1 = bias[(r1 / Tv) & (Cv - 1)];
        float bv2 = bias[(r2 / Tv) & (Cv - 1)];
        #pragma unroll
        for (int nt = 0; nt < 4; nt++) {
            int c = bn * 128 + wn + 8 * nt + 2 * tg;
            float z10, z11, z20, z21;
            if (RF32) {
                const float* rp = (const float*)residv;
                float2 a = *reinterpret_cast<const float2*>(rp + (size_t)r1 * Nv + c);
                float2 b2_ = *reinterpret_cast<const float2*>(rp + (size_t)r2 * Nv + c);
                z10 = a.x;  z11 = a.y;  z20 = b2_.x; z21 = b2_.y;
            } else {
                const __half* rp = (const __half*)residv;
                __half2 a = *reinterpret_cast<const __half2*>(rp + (size_t)r1 * Nv + c);
                __half2 b2_ = *reinterpret_cast<const __half2*>(rp + (size_t)r2 * Nv + c);
                z10 = __low2float(a);  z11 = __high2float(a);
                z20 = __low2float(b2_); z21 = __high2float(b2_);
            }
            float v0 = fmaxf(acc[mt][nt][0] + bv1 + z10, 0.f);
            float v1 = fmaxf(acc[mt][nt][1] + bv1 + z11, 0.f);
            float v2 = fmaxf(acc[mt][nt][2] + bv2 + z20, 0.f);
            float v3 = fmaxf(acc[mt][nt][3] + bv2 + z21, 0.f);
            *reinterpret_cast<__half2*>(Cout + (size_t)r1 * Nv + c) = __floats2half2_rn(v0, v1);
            *reinterpret_cast<__half2*>(Cout + (size_t)r2 * Nv + c) = __floats2half2_rn(v2, v3);
        }
    }
}

// ---------------- kernel D: final FC via fp16 mma ----------------
#define FC_WROW 144
#define FC_XROW 272

__global__ __launch_bounds__(256, 2) void fc_mma(const __half* __restrict__ X2c,
                                                 const __half* __restrict__ fcwH,
                                                 const float* __restrict__ fcb,
                                                 float*       __restrict__ out)
{
    __shared__ __half Ws[OUTv * (FC_WROW/2)];
    __shared__ __half Xs[Cv * (FC_XROW/2)];
    __shared__ float  bsf[OUTv];
    const uint32_t smW = (uint32_t)__cvta_generic_to_shared(Ws);
    const uint32_t smX = (uint32_t)__cvta_generic_to_shared(Xs);

    const int bt = blockIdx.x;            // local to chunk
    const int b  = bt / Tv;
    const int t  = bt % Tv;
    const int n0 = blockIdx.y * 128;
    const int tid  = threadIdx.x;
    const int wid  = tid >> 5;
    const int lane = tid & 31;
    const int gq = lane >> 2;
    const int tg = lane & 3;
    const int wm = (wid & 3) * 32;
    const int wn = (wid >> 2) * 32;

    #pragma unroll
    for (int l = 0; l < 2; l++) {
        int slot = tid + 256 * l;
        int j = slot >> 3, q = slot & 7;
        cp16(smW + (uint32_t)(j * FC_WROW + q * 16), fcwH + j * Cv + q * 8);
    }
    #pragma unroll
    for (int l = 0; l < 4; l++) {
        int slot = tid + 256 * l;
        int o = slot >> 4, q = slot & 15;
        cp16(smX + (uint32_t)(o * FC_XROW + q * 16),
             X2c + ((size_t)(b * Cv + o) * Tv + t) * Nv + n0 + q * 8);
    }
    if (tid < OUTv) bsf[tid] = fcb[tid];
    cp_commit();
    asm volatile("cp.async.wait_group 0;" ::: "memory");
    __syncthreads();

    float acc[2][4][4];
    #pragma unroll
    for (int i = 0; i < 2; i++)
        #pragma unroll
        for (int j = 0; j < 4; j++)
            #pragma unroll
            for (int q = 0; q < 4; q++) acc[i][j][q] = 0.f;

    const int rowAt = (lane & 7) + ((lane >> 4) & 1) * 8;
    const int colAt = ((lane >> 3) & 1) * 16;
    const int rowB = (lane & 7) + ((lane >> 4) & 1) * 8;
    const int colB = ((lane >> 3) & 1) * 16;

    #pragma unroll
    for (int ks = 0; ks < 4; ks++) {
        uint32_t af[2][4];
        #pragma unroll
        for (int mt = 0; mt < 2; mt++)
            ldsm_x4_t(af[mt][0], af[mt][1], af[mt][2], af[mt][3],
                      smX + (uint32_t)((ks*16 + rowAt) * FC_XROW + (wm + 16*mt) * 2 + colAt));
        uint32_t bf[4][2];
        #pragma unroll
        for (int ntp = 0; ntp < 2; ntp++)
            ldsm_x4(bf[2*ntp][0], bf[2*ntp][1], bf[2*ntp+1][0], bf[2*ntp+1][1],
                    smW + (uint32_t)((wn + 16*ntp + rowB) * FC_WROW + ks * 32 + colB));
        #pragma unroll
        for (int mt = 0; mt < 2; mt++)
            #pragma unroll
            for (int nt = 0; nt < 4; nt++)
                mma_f16(acc[mt][nt][0], acc[mt][nt][1], acc[mt][nt][2], acc[mt][nt][3],
                        af[mt][0], af[mt][1], af[mt][2], af[mt][3],
                        bf[nt][0], bf[nt][1]);
    }

    #pragma unroll
    for (int mt = 0; mt < 2; mt++) {
        int nr1 = wm + 16 * mt + gq;
        int nr2 = nr1 + 8;
        size_t o1 = ((size_t)bt * Nv + n0 + nr1) * OUTv;
        size_t o2 = ((size_t)bt * Nv + n0 + nr2) * OUTv;
        #pragma unroll
        for (int nt = 0; nt < 4; nt++) {
            int j = wn + 8 * nt + 2 * tg;
            float bj0 = bsf[j], bj1 = bsf[j + 1];
            float2 v1 = make_float2(acc[mt][nt][0] + bj0, acc[mt][nt][1] + bj1);
            float2 v2 = make_float2(acc[mt][nt][2] + bj0, acc[mt][nt][3] + bj1);
            *reinterpret_cast<float2*>(out + o1 + j) = v1;
            *reinterpret_cast<float2*>(out + o2 + j) = v2;
        }
    }
}

// ---------------- static-init module materialization ----------------
namespace {
struct ModuleLoader {
    ModuleLoader() {
        cudaFree(0);
        cudaGetSymbolAddress((void**)&pLkH, g_LkH);
        cudaGetSymbolAddress((void**)&pYH,  g_YH);
        cudaGetSymbolAddress((void**)&pX1,  g_X1);
        cudaGetSymbolAddress((void**)&pX2,  g_X2);
        cudaGetSymbolAddress((void**)&pTh1, g_Th1);
        cudaGetSymbolAddress((void**)&pTh2, g_Th2);
        cudaGetSymbolAddress((void**)&pFcW, g_FcW);
        cudaMemset(pLkH, 0, 4);
        cudaMemset(pYH,  0, 4);
        cudaMemset(pX1,  0, 4);
        cudaMemset(pX2,  0, 4);
        cudaMemset(pTh1, 0, 4);
        cudaMemset(pTh2, 0, 4);
        cudaMemset(pFcW, 0, 4);
        cudaFuncSetAttribute(gemm_f16<true>,  cudaFuncAttributeMaxDynamicSharedMemorySize, GSMEM_BYTES);
        cudaFuncSetAttribute(gemm_f16<false>, cudaFuncAttributeMaxDynamicSharedMemorySize, GSMEM_BYTES);
        cudaFuncSetAttribute(channel_mix_f16<true>,  cudaFuncAttributeMaxDynamicSharedMemorySize, CM_SMEM);
        cudaFuncSetAttribute(channel_mix_f16<false>, cudaFuncAttributeMaxDynamicSharedMemorySize, CM_SMEM);
        for (int c = 0; c < NCHUNK; c++) {
            cudaStreamCreateWithFlags(&g_str[c], cudaStreamNonBlocking);
            cudaEventCreateWithFlags(&g_evD[c], cudaEventDisableTiming);
        }
        cudaEventCreateWithFlags(&g_evP, cudaEventDisableTiming);
        cudaDeviceSynchronize();
    }
};
ModuleLoader g_loader;
}

// ---------------- launch: dual-stream chunked pipeline ----------------
extern "C" void kernel_launch(void* const* d_in, const int* in_sizes, int n_in,
                              void* d_out, int out_size)
{
    const float* x      = (const float*)d_in[0];
    const float* Lk     = (const float*)d_in[1];
    const float* theta1 = (const float*)d_in[2];
    const float* b1     = (const float*)d_in[3];
    const float* theta2 = (const float*)d_in[4];
    const float* b2     = (const float*)d_in[5];
    const float* fc_w   = (const float*)d_in[6];
    const float* fc_b   = (const float*)d_in[7];
    float* out = (float*)d_out;

    // prep on capture (default) stream, then fork
    prep_all<<<3072 + 96 + 1, 256>>>(Lk, theta1, theta2, fc_w, pLkH, pTh1, pTh2, pFcW);
    cudaEventRecord(g_evP, 0);

    for (int c = 0; c < NCHUNK; c++) {
        cudaStream_t s = g_str[c];
        cudaStreamWaitEvent(s, g_evP, 0);
        const size_t ro = (size_t)c * CROWS;            // row offset

        const float*  xc  = x   + ro * Nv;              // fp32 input rows
        __half*       Yc  = pYH + ro * Kdim;
        __half*       X1c = pX1 + ro * Nv;
        __half*       X2c = pX2 + ro * Nv;
        float*        oc  = out + (size_t)c * CBT * Nv * OUTv;

        channel_mix_f16<true><<<dim3(CBT, Nv / 256), 256, CM_SMEM, s>>>(xc, pTh1, Yc);
        gemm_f16<true><<<dim3(8, CROWS / GBM), 256, GSMEM_BYTES, s>>>(Yc, pLkH, b1, xc, X1c);

        channel_mix_f16<false><<<dim3(CBT, Nv / 256), 256, CM_SMEM, s>>>(X1c, pTh2, Yc);
        gemm_f16<false><<<dim3(8, CROWS / GBM), 256, GSMEM_BYTES, s>>>(Yc, pLkH, b2, X1c, X2c);

        fc_mma<<<dim3(CBT, Nv / 128), 256, 0, s>>>(X2c, pFcW, fc_b, oc);
        cudaEventRecord(g_evD[c], s);
    }

    // join back onto the capture stream
    for (int c = 0; c < NCHUNK; c++)
        cudaStreamWaitEvent((cudaStream_t)0, g_evD[c], 0);
}